// round 15
// baseline (speedup 1.0000x reference)
#include <cuda_runtime.h>
#include <cuda_bf16.h>
#include <cooperative_groups.h>
namespace cg = cooperative_groups;

#define LDIM 4096
#define BDIM 32
#define CIN  64
#define ODIM 128
#define KDIM 9
#define OCHUNK 64

typedef unsigned long long u64;

// Scratch (allocation-free rule: __device__ globals)
__device__ float4 g_xs4[BDIM * (LDIM / 4)];   // fully reduced xs, 512 KB
__device__ float4 g_wb4[ODIM * 3];            // padded rows: w0..3|w4..7|w8,b,0,0
__device__ float  g_evinv;                    // 1 / ||err_vector||

// ---- packed f32x2 helpers ----
__device__ __forceinline__ u64 pack2(float lo, float hi) {
    u64 r; asm("mov.b64 %0, {%1,%2};" : "=l"(r) : "f"(lo), "f"(hi)); return r;
}
__device__ __forceinline__ u64 ffma2(u64 a, u64 b, u64 c) {
    u64 d; asm("fma.rn.f32x2 %0, %1, %2, %3;" : "=l"(d) : "l"(a), "l"(b), "l"(c));
    return d;
}
__device__ __forceinline__ float2 unpack2(u64 v) {
    float2 f; asm("mov.b64 {%0,%1}, %2;" : "=f"(f.x), "=f"(f.y) : "l"(v)); return f;
}

// ---------------------------------------------------------------------------
// Single cooperative kernel. grid = 512 blocks x 256 thr (4 blocks/SM).
// Phase 1 (all 512): xs[b][l-slice] = sum over ALL 64 channels (smem combine);
//                    block 0 additionally normalizes ev + weights.
// grid.sync()
// Phase 2 (blocks 0..255): R10 inner loop — stage xs, gather once, f32x2
//                    o-loop with register-packed weights, streaming STG.128.
// ---------------------------------------------------------------------------
__global__ __launch_bounds__(256, 4) void gmconv_fused_kernel(
    const float* __restrict__ x,
    const float* __restrict__ wc,
    const float* __restrict__ ev,
    const float* __restrict__ bias,
    const int*   __restrict__ idxm,
    float*       __restrict__ out) {

    __shared__ float4 s_buf[LDIM / 4];            // 16 KB, reused both phases
    float* s_xs = reinterpret_cast<float*>(s_buf);

    const int bx = blockIdx.x;
    const int t  = threadIdx.x;

    // ================= Phase 1: channel reduction =================
    {
        const int b  = bx >> 4;                   // 0..31
        const int ls = bx & 15;                   // l-slice: 64 float4 each
        const int tl = t & 63;
        const int tc = t >> 6;                    // channel group 0..3 (16 ch)
        const int l4 = ls * 64 + tl;              // 0..1023

        const float4* xp = reinterpret_cast<const float4*>(x) +
                           ((size_t)b * CIN + tc * 16) * (LDIM / 4) + l4;
        float4 a0 = make_float4(0.f, 0.f, 0.f, 0.f);
        float4 a1 = make_float4(0.f, 0.f, 0.f, 0.f);
#pragma unroll
        for (int i = 0; i < 16; i += 2) {
            float4 v0 = __ldg(xp + (i    ) * (LDIM / 4));
            float4 v1 = __ldg(xp + (i + 1) * (LDIM / 4));
            a0.x += v0.x; a0.y += v0.y; a0.z += v0.z; a0.w += v0.w;
            a1.x += v1.x; a1.y += v1.y; a1.z += v1.z; a1.w += v1.w;
        }
        a0.x += a1.x; a0.y += a1.y; a0.z += a1.z; a0.w += a1.w;
        s_buf[t] = a0;
        __syncthreads();
        if (t < 64) {
            float4 r0 = s_buf[t], r1 = s_buf[t + 64],
                   r2 = s_buf[t + 128], r3 = s_buf[t + 192];
            g_xs4[b * (LDIM / 4) + l4] = make_float4(
                r0.x + r1.x + r2.x + r3.x, r0.y + r1.y + r2.y + r3.y,
                r0.z + r1.z + r2.z + r3.z, r0.w + r1.w + r2.w + r3.w);
        }
        __syncthreads();
    }

    // ---- block 0: ev norm + weight normalization/packing ----
    if (bx == 0) {
        float ssq = 0.f;
        for (int i = t; i < LDIM; i += 256) { float v = ev[i]; ssq += v * v; }
        s_xs[t] = ssq;
        __syncthreads();
        for (int s = 128; s > 0; s >>= 1) {
            if (t < s) s_xs[t] += s_xs[t + s];
            __syncthreads();
        }
        if (t == 0) g_evinv = rsqrtf(s_xs[0]);

        if (t < ODIM) {
            float w[KDIM];
            float n = 0.f;
#pragma unroll
            for (int k = 0; k < KDIM; ++k) { w[k] = wc[t * KDIM + k]; n += w[k] * w[k]; }
            float inv = rsqrtf(n);
            g_wb4[t * 3 + 0] = make_float4(w[0]*inv, w[1]*inv, w[2]*inv, w[3]*inv);
            g_wb4[t * 3 + 1] = make_float4(w[4]*inv, w[5]*inv, w[6]*inv, w[7]*inv);
            g_wb4[t * 3 + 2] = make_float4(w[8]*inv, bias[t], 0.f, 0.f);
        }
    }

    cg::this_grid().sync();

    // ================= Phase 2: blocks 0..255 =================
    if (bx >= 256) return;

    const int tile  = bx & 3;                     // 0..3 (1024 l each)
    const int b     = (bx >> 2) & 31;             // 0..31
    const int obase = (bx >> 7) * OCHUNK;         // 0, 64

    // stage xs[b] (single read, already fully reduced)
    {
        const float4* g4 = &g_xs4[b * (LDIM / 4)];
        for (int i = t; i < LDIM / 4; i += 256) s_buf[i] = __ldg(&g4[i]);
    }
    __syncthreads();

    const int l = tile * 1024 + t * 4;
    const float evinv = g_evinv;
    float4 e4 = __ldg(reinterpret_cast<const float4*>(ev + l));
    const float ex = e4.x * evinv, ey = e4.y * evinv,
                ez = e4.z * evinv, ew = e4.w * evinv;

    // gather 9 neighbor quads from smem, pre-scaled, packed into f32x2 pairs
    u64 g01[KDIM], g23[KDIM];
#pragma unroll
    for (int k = 0; k < KDIM; ++k) {
        int4 id = __ldg(reinterpret_cast<const int4*>(idxm + k * LDIM + l));
        g01[k] = pack2(s_xs[id.x] * ex, s_xs[id.y] * ey);
        g23[k] = pack2(s_xs[id.z] * ez, s_xs[id.w] * ew);
    }

    float* outp = out + ((size_t)b * ODIM + obase) * LDIM + l;
#pragma unroll 2
    for (int o = 0; o < OCHUNK; ++o) {
        // 3 uniform LDG.128 (L1/L2-hot 6 KB table, broadcast across warp)
        const float4 wa = __ldg(&g_wb4[(obase + o) * 3 + 0]);
        const float4 wb = __ldg(&g_wb4[(obase + o) * 3 + 1]);
        const float4 wcv = __ldg(&g_wb4[(obase + o) * 3 + 2]);

        u64 acc01 = pack2(wcv.y, wcv.y);          // {bias,bias}
        u64 acc23 = acc01;

        u64 w2;
        w2 = pack2(wa.x, wa.x); acc01 = ffma2(w2, g01[0], acc01); acc23 = ffma2(w2, g23[0], acc23);
        w2 = pack2(wa.y, wa.y); acc01 = ffma2(w2, g01[1], acc01); acc23 = ffma2(w2, g23[1], acc23);
        w2 = pack2(wa.z, wa.z); acc01 = ffma2(w2, g01[2], acc01); acc23 = ffma2(w2, g23[2], acc23);
        w2 = pack2(wa.w, wa.w); acc01 = ffma2(w2, g01[3], acc01); acc23 = ffma2(w2, g23[3], acc23);
        w2 = pack2(wb.x, wb.x); acc01 = ffma2(w2, g01[4], acc01); acc23 = ffma2(w2, g23[4], acc23);
        w2 = pack2(wb.y, wb.y); acc01 = ffma2(w2, g01[5], acc01); acc23 = ffma2(w2, g23[5], acc23);
        w2 = pack2(wb.z, wb.z); acc01 = ffma2(w2, g01[6], acc01); acc23 = ffma2(w2, g23[6], acc23);
        w2 = pack2(wb.w, wb.w); acc01 = ffma2(w2, g01[7], acc01); acc23 = ffma2(w2, g23[7], acc23);
        w2 = pack2(wcv.x, wcv.x); acc01 = ffma2(w2, g01[8], acc01); acc23 = ffma2(w2, g23[8], acc23);

        float2 r01 = unpack2(acc01);
        float2 r23 = unpack2(acc23);
        __stcs(reinterpret_cast<float4*>(outp + (size_t)o * LDIM),
               make_float4(r01.x, r01.y, r23.x, r23.y));   // streaming STG.128
    }
}

// ---------------------------------------------------------------------------
extern "C" void kernel_launch(void* const* d_in, const int* in_sizes, int n_in,
                              void* d_out, int out_size) {
    const float* x    = nullptr;
    const float* wc   = nullptr;
    const float* ev   = nullptr;
    const float* bias = nullptr;
    const int*   idxm = nullptr;

    for (int i = 0; i < n_in; ++i) {
        switch (in_sizes[i]) {
            case BDIM * CIN * LDIM: x    = (const float*)d_in[i]; break;  // 8388608
            case ODIM * KDIM:       wc   = (const float*)d_in[i]; break;  // 1152
            case LDIM:              ev   = (const float*)d_in[i]; break;  // 4096
            case ODIM:              bias = (const float*)d_in[i]; break;  // 128
            case KDIM * LDIM:       idxm = (const int*)  d_in[i]; break;  // 36864
            default: break;
        }
    }

    float* out = (float*)d_out;

    void* args[] = { (void*)&x, (void*)&wc, (void*)&ev, (void*)&bias,
                     (void*)&idxm, (void*)&out };
    cudaLaunchCooperativeKernel((void*)gmconv_fused_kernel,
                                dim3(512, 1, 1), dim3(256, 1, 1),
                                args, 0, (cudaStream_t)0);
}

// round 16
// speedup vs baseline: 1.8609x; 1.8609x over previous
#include <cuda_runtime.h>
#include <cuda_bf16.h>

#define LDIM 4096
#define BDIM 32
#define CIN  64
#define ODIM 128
#define KDIM 9
#define CCHUNKS 2               // split-K chunks over channel dim
#define CPER   (CIN / CCHUNKS)  // 32 channels per chunk
#define OCHUNK 64               // outputs per main-kernel block

typedef unsigned long long u64;

// Scratch (allocation-free rule: __device__ globals)
__device__ float  g_part[CCHUNKS * BDIM * LDIM]; // partial channel sums, 1 MB
__device__ float4 g_wb4[ODIM * 3];               // padded rows: w0..3|w4..7|w8,b,0,0
__device__ float  g_evinv;                       // 1 / ||err_vector||

// ---- packed f32x2 helpers ----
__device__ __forceinline__ u64 pack2(float lo, float hi) {
    u64 r; asm("mov.b64 %0, {%1,%2};" : "=l"(r) : "f"(lo), "f"(hi)); return r;
}
__device__ __forceinline__ u64 ffma2(u64 a, u64 b, u64 c) {
    u64 d; asm("fma.rn.f32x2 %0, %1, %2, %3;" : "=l"(d) : "l"(a), "l"(b), "l"(c));
    return d;
}
__device__ __forceinline__ float2 unpack2(u64 v) {
    float2 f; asm("mov.b64 {%0,%1}, %2;" : "=f"(f.x), "=f"(f.y) : "l"(v)); return f;
}

// ---------------------------------------------------------------------------
// Kernel A: split-K channel reduction (512 blocks x 128 thr) + prep (block 512)
//   identical to R4/R10 (best measured wallclock config)
// ---------------------------------------------------------------------------
__global__ __launch_bounds__(128) void reduce_prep_kernel(
    const float* __restrict__ x,
    const float* __restrict__ wc,
    const float* __restrict__ ev,
    const float* __restrict__ bias) {

    const int bx = blockIdx.x;
    const int t  = threadIdx.x;

    if (bx < BDIM * 16) {                      // 512 reduce blocks
        const int b   = bx >> 4;               // 0..31
        const int sub = bx & 15;
        const int lt  = sub >> 1;              // l-tile 0..7 (128 float4 each)
        const int cc  = sub & 1;               // channel chunk 0..1
        const int l4  = lt * 128 + t;          // 0..1023

        const float4* xp = reinterpret_cast<const float4*>(x) +
                           ((size_t)b * CIN + cc * CPER) * (LDIM / 4) + l4;
        float4 a0 = make_float4(0.f, 0.f, 0.f, 0.f);
        float4 a1 = make_float4(0.f, 0.f, 0.f, 0.f);
#pragma unroll 8
        for (int i = 0; i < CPER; i += 2) {
            float4 v0 = __ldg(xp + (i    ) * (LDIM / 4));
            float4 v1 = __ldg(xp + (i + 1) * (LDIM / 4));
            a0.x += v0.x; a0.y += v0.y; a0.z += v0.z; a0.w += v0.w;
            a1.x += v1.x; a1.y += v1.y; a1.z += v1.z; a1.w += v1.w;
        }
        a0.x += a1.x; a0.y += a1.y; a0.z += a1.z; a0.w += a1.w;
        reinterpret_cast<float4*>(g_part)[(cc * BDIM + b) * (LDIM / 4) + l4] = a0;
        return;
    }

    // ---- prep block (128 threads) ----
    __shared__ float red[128];
    float ssq = 0.f;
    for (int i = t; i < LDIM; i += 128) { float v = ev[i]; ssq += v * v; }
    red[t] = ssq;
    __syncthreads();
    for (int s = 64; s > 0; s >>= 1) {
        if (t < s) red[t] += red[t + s];
        __syncthreads();
    }
    if (t == 0) g_evinv = rsqrtf(red[0]);

    // one thread per output channel (128 threads = ODIM); padded float4 rows
    {
        float w[KDIM];
        float n = 0.f;
#pragma unroll
        for (int k = 0; k < KDIM; ++k) { w[k] = wc[t * KDIM + k]; n += w[k] * w[k]; }
        float inv = rsqrtf(n);
        g_wb4[t * 3 + 0] = make_float4(w[0]*inv, w[1]*inv, w[2]*inv, w[3]*inv);
        g_wb4[t * 3 + 1] = make_float4(w[4]*inv, w[5]*inv, w[6]*inv, w[7]*inv);
        g_wb4[t * 3 + 2] = make_float4(w[8]*inv, bias[t], 0.f, 0.f);
    }
}

// ---------------------------------------------------------------------------
// Kernel B: out[b,o,l] = ev[l]/||ev|| * sum_k w[o,k]*xs[b, idx[k,l]] + bias[o]
// grid: (4 l-tiles of 1024, 32 b, 2 o-chunks of 64) = 256 blocks x 256 thr.
// R10 inner loop: lpt=4 as two f32x2 pairs; weights via 3 uniform __ldg
// float4 from the 6KB g_wb4 table (L1/L2-hot, warp-broadcast) -> no const
// memcpy node in the graph. Streaming STG.128.
// ---------------------------------------------------------------------------
__global__ __launch_bounds__(256, 2) void gmconv_main_kernel(
    const int*   __restrict__ idxm,
    const float* __restrict__ ev,
    float*       __restrict__ out) {

    __shared__ float s_xs[LDIM];                    // 16 KB (only smem)

    const int tile  = blockIdx.x;                   // 0..3
    const int b     = blockIdx.y;                   // 0..31
    const int obase = blockIdx.z * OCHUNK;          // 0, 64
    const int t     = threadIdx.x;

    // stage xs[b] = p0 + p1 (L2-resident partials)
    {
        float4* s4 = reinterpret_cast<float4*>(s_xs);
        const float4* g4 = reinterpret_cast<const float4*>(g_part);
#pragma unroll
        for (int i = t; i < LDIM / 4; i += 256) {
            float4 p0 = __ldg(&g4[(0 * BDIM + b) * (LDIM / 4) + i]);
            float4 p1 = __ldg(&g4[(1 * BDIM + b) * (LDIM / 4) + i]);
            s4[i] = make_float4(p0.x + p1.x, p0.y + p1.y,
                                p0.z + p1.z, p0.w + p1.w);
        }
    }
    __syncthreads();

    const int l = tile * 1024 + t * 4;
    const float evinv = g_evinv;
    float4 e4 = __ldg(reinterpret_cast<const float4*>(ev + l));
    const float ex = e4.x * evinv, ey = e4.y * evinv,
                ez = e4.z * evinv, ew = e4.w * evinv;

    // gather 9 neighbor quads from smem, pre-scaled, packed into f32x2 pairs
    u64 g01[KDIM], g23[KDIM];
#pragma unroll
    for (int k = 0; k < KDIM; ++k) {
        int4 id = __ldg(reinterpret_cast<const int4*>(idxm + k * LDIM + l));
        g01[k] = pack2(s_xs[id.x] * ex, s_xs[id.y] * ey);
        g23[k] = pack2(s_xs[id.z] * ez, s_xs[id.w] * ew);
    }

    float* outp = out + ((size_t)b * ODIM + obase) * LDIM + l;
#pragma unroll 2
    for (int o = 0; o < OCHUNK; ++o) {
        // 3 uniform LDG.128 from the hot 6 KB weight table
        const float4 wa  = __ldg(&g_wb4[(obase + o) * 3 + 0]);
        const float4 wb  = __ldg(&g_wb4[(obase + o) * 3 + 1]);
        const float4 wcv = __ldg(&g_wb4[(obase + o) * 3 + 2]);

        u64 acc01 = pack2(wcv.y, wcv.y);            // {bias,bias}
        u64 acc23 = acc01;

        u64 w2;
        w2 = pack2(wa.x, wa.x);  acc01 = ffma2(w2, g01[0], acc01); acc23 = ffma2(w2, g23[0], acc23);
        w2 = pack2(wa.y, wa.y);  acc01 = ffma2(w2, g01[1], acc01); acc23 = ffma2(w2, g23[1], acc23);
        w2 = pack2(wa.z, wa.z);  acc01 = ffma2(w2, g01[2], acc01); acc23 = ffma2(w2, g23[2], acc23);
        w2 = pack2(wa.w, wa.w);  acc01 = ffma2(w2, g01[3], acc01); acc23 = ffma2(w2, g23[3], acc23);
        w2 = pack2(wb.x, wb.x);  acc01 = ffma2(w2, g01[4], acc01); acc23 = ffma2(w2, g23[4], acc23);
        w2 = pack2(wb.y, wb.y);  acc01 = ffma2(w2, g01[5], acc01); acc23 = ffma2(w2, g23[5], acc23);
        w2 = pack2(wb.z, wb.z);  acc01 = ffma2(w2, g01[6], acc01); acc23 = ffma2(w2, g23[6], acc23);
        w2 = pack2(wb.w, wb.w);  acc01 = ffma2(w2, g01[7], acc01); acc23 = ffma2(w2, g23[7], acc23);
        w2 = pack2(wcv.x, wcv.x); acc01 = ffma2(w2, g01[8], acc01); acc23 = ffma2(w2, g23[8], acc23);

        float2 r01 = unpack2(acc01);
        float2 r23 = unpack2(acc23);
        __stcs(reinterpret_cast<float4*>(outp + (size_t)o * LDIM),
               make_float4(r01.x, r01.y, r23.x, r23.y));   // streaming STG.128
    }
}

// ---------------------------------------------------------------------------
extern "C" void kernel_launch(void* const* d_in, const int* in_sizes, int n_in,
                              void* d_out, int out_size) {
    const float* x    = nullptr;
    const float* wc   = nullptr;
    const float* ev   = nullptr;
    const float* bias = nullptr;
    const int*   idxm = nullptr;

    for (int i = 0; i < n_in; ++i) {
        switch (in_sizes[i]) {
            case BDIM * CIN * LDIM: x    = (const float*)d_in[i]; break;  // 8388608
            case ODIM * KDIM:       wc   = (const float*)d_in[i]; break;  // 1152
            case LDIM:              ev   = (const float*)d_in[i]; break;  // 4096
            case ODIM:              bias = (const float*)d_in[i]; break;  // 128
            case KDIM * LDIM:       idxm = (const int*)  d_in[i]; break;  // 36864
            default: break;
        }
    }

    float* out = (float*)d_out;

    reduce_prep_kernel<<<BDIM * 16 + 1, 128>>>(x, wc, ev, bias);
    gmconv_main_kernel<<<dim3(4, BDIM, 2), 256>>>(idxm, ev, out);
}